// round 2
// baseline (speedup 1.0000x reference)
#include <cuda_runtime.h>
#include <math.h>

#define Nn 50000
#define Ee 800000
#define Ff 64
#define Tt 3
#define NSs 64
#define NTOT (4*Nn)

// ---------------- scratch (device globals; no allocation allowed) ----------------
__device__ __align__(16) float g_trans[Tt*Nn*Ff];
__device__ float g_fnorm[Nn];
__device__ float g_tnorm[Tt*Nn];
__device__ unsigned char g_mask[Ee];
__device__ int g_indeg[Nn];
__device__ int g_off[Nn+1];
__device__ int g_fill[Nn];
__device__ int g_eid[Ee];
__device__ float g_dinv[4*Nn];
__device__ __align__(16) float g_xw0[Nn*Ff];
__device__ __align__(16) float g_h1[NTOT*Ff];
__device__ __align__(16) float g_xw1[NTOT*Ff];
__device__ __align__(16) float g_x2[NTOT*Ff];
__device__ int g_cls[NTOT];
__device__ __align__(16) float g_hyper[NSs*Ff];
__device__ float g_colsum[NSs];

// ---------------- init ----------------
__global__ void init_kernel()
{
    int i = blockIdx.x * blockDim.x + threadIdx.x;
    if (i < Nn) { g_indeg[i] = 0; g_fill[i] = 0; }
    if (i < NSs*Ff) g_hyper[i] = 0.0f;
    if (i < NSs) g_colsum[i] = (float)Nn;
}

// ---------------- generic 64x64 GEMM: out[r] = (relu?)X[r] @ W (+bias) ----------------
__global__ void gemm64(const float* __restrict__ X, const float* __restrict__ W,
                       const float* __restrict__ bias, float* __restrict__ out,
                       int rows, int relu_in)
{
    __shared__ float Xs[64][65];
    __shared__ float Ws[64][64];
    int tid = threadIdx.x;                 // 256 threads
    int row0 = blockIdx.x * 64;
    for (int i = tid; i < 4096; i += 256) Ws[i >> 6][i & 63] = W[i];
    for (int i = tid; i < 4096; i += 256) {
        int r = i >> 6, c = i & 63;
        int gr = row0 + r;
        float v = (gr < rows) ? X[(size_t)gr*64 + c] : 0.0f;
        if (relu_in) v = fmaxf(v, 0.0f);
        Xs[r][c] = v;
    }
    __syncthreads();
    int r = tid & 63;
    int g = tid >> 6;                      // columns g*16 .. g*16+15
    float acc[16];
#pragma unroll
    for (int j = 0; j < 16; j++) acc[j] = 0.0f;
#pragma unroll
    for (int k = 0; k < 64; k++) {
        float xv = Xs[r][k];
        const float* wrow = &Ws[k][g*16];
#pragma unroll
        for (int j = 0; j < 16; j++) acc[j] += xv * wrow[j];
    }
    int gr = row0 + r;
    if (gr < rows) {
        float* o = out + (size_t)gr*64 + g*16;
#pragma unroll
        for (int j = 0; j < 16; j++) {
            float v = acc[j];
            if (bias) v += bias[g*16 + j];
            o[j] = v;
        }
    }
}

// ---------------- row norms (features + trans), eps-clamped ----------------
__global__ void norms_kernel(const float* __restrict__ feat)
{
    int w = (blockIdx.x * blockDim.x + threadIdx.x) >> 5;
    int lane = threadIdx.x & 31;
    if (w >= 4*Nn) return;
    const float* p = (w < Nn) ? (feat + (size_t)w*64) : (g_trans + (size_t)(w - Nn)*64);
    float2 v = ((const float2*)p)[lane];
    float s = v.x*v.x + v.y*v.y;
#pragma unroll
    for (int o = 16; o; o >>= 1) s += __shfl_xor_sync(0xffffffffu, s, o);
    if (lane == 0) {
        float nrm = fmaxf(sqrtf(s), 1e-8f);
        if (w < Nn) g_fnorm[w] = nrm; else g_tnorm[w - Nn] = nrm;
    }
}

// ---------------- per-edge cosine sims -> masks; indegree count ----------------
__global__ void edge_kernel(const int* __restrict__ ei, const float* __restrict__ feat)
{
    int w = (blockIdx.x * blockDim.x + threadIdx.x) >> 5;
    int lane = threadIdx.x & 31;
    if (w >= Ee) return;
    int s = ei[w], d = ei[Ee + w];
    float2 a  = ((const float2*)(feat + (size_t)s*64))[lane];
    float2 b  = ((const float2*)(feat + (size_t)d*64))[lane];
    float2 t0 = ((const float2*)(g_trans + (size_t)s*64))[lane];
    float2 t1 = ((const float2*)(g_trans + (size_t)(Nn + s)*64))[lane];
    float2 t2 = ((const float2*)(g_trans + (size_t)(2*Nn + s)*64))[lane];
    float d0 = a.x*b.x + a.y*b.y;
    float e0 = t0.x*b.x + t0.y*b.y;
    float e1 = t1.x*b.x + t1.y*b.y;
    float e2 = t2.x*b.x + t2.y*b.y;
#pragma unroll
    for (int o = 16; o; o >>= 1) {
        d0 += __shfl_xor_sync(0xffffffffu, d0, o);
        e0 += __shfl_xor_sync(0xffffffffu, e0, o);
        e1 += __shfl_xor_sync(0xffffffffu, e1, o);
        e2 += __shfl_xor_sync(0xffffffffu, e2, o);
    }
    if (lane == 0) {
        float ns = g_fnorm[s], nd = g_fnorm[d];
        float sim0 = d0 / (ns * nd);
        unsigned m = 0;
        if (e0 / (g_tnorm[s]        * nd) > sim0) m |= 1u;
        if (e1 / (g_tnorm[Nn + s]   * nd) > sim0) m |= 2u;
        if (e2 / (g_tnorm[2*Nn + s] * nd) > sim0) m |= 4u;
        g_mask[w] = (unsigned char)m;
        atomicAdd(&g_indeg[d], 1);
    }
}

// ---------------- exclusive scan of indeg (single block) ----------------
__global__ void scan_kernel()
{
    __shared__ int sm[1024];
    __shared__ int carry_s;
    int tid = threadIdx.x;
    if (tid == 0) carry_s = 0;
    __syncthreads();
    for (int base = 0; base < Nn; base += 1024) {
        int idx = base + tid;
        int x = (idx < Nn) ? g_indeg[idx] : 0;
        sm[tid] = x;
        __syncthreads();
        for (int o = 1; o < 1024; o <<= 1) {
            int v = (tid >= o) ? sm[tid - o] : 0;
            __syncthreads();
            sm[tid] += v;
            __syncthreads();
        }
        if (idx < Nn) g_off[idx] = carry_s + sm[tid] - x;
        __syncthreads();
        if (tid == 0) carry_s += sm[1023];
        __syncthreads();
    }
    if (tid == 0) g_off[Nn] = carry_s;
}

// ---------------- CSR fill ----------------
__global__ void fill_kernel(const int* __restrict__ ei)
{
    int e = blockIdx.x * blockDim.x + threadIdx.x;
    if (e >= Ee) return;
    int d = ei[Ee + e];
    int p = g_off[d] + atomicAdd(&g_fill[d], 1);
    g_eid[p] = e;
}

// ---------------- degrees -> dinv per replica ----------------
__global__ void dinv_kernel()
{
    int i = blockIdx.x * blockDim.x + threadIdx.x;
    if (i >= Nn) return;
    int beg = g_off[i], end = g_off[i+1];
    int c1 = 0, c2 = 0, c3 = 0;
    for (int k = beg; k < end; k++) {
        unsigned m = g_mask[g_eid[k]];
        c1 += (m)      & 1u;
        c2 += (m >> 1) & 1u;
        c3 += (m >> 2) & 1u;
    }
    g_dinv[i]        = 1.0f / sqrtf((float)(end - beg) + 1.0f);
    g_dinv[Nn + i]   = 1.0f / sqrtf((float)c1 + 2.0f);
    g_dinv[2*Nn + i] = 1.0f / sqrtf((float)c2 + 2.0f);
    g_dinv[3*Nn + i] = 1.0f / sqrtf((float)c3 + 2.0f);
}

// ---------------- GCN layer: gather-side reduction, warp per node, 4 replicas fused ----------------
__global__ void gcn_layer_kernel(const int* __restrict__ srcArr,
                                 const float* __restrict__ XW,      // replica-0 gather source (N x 64)
                                 const float* __restrict__ XWfull,  // full (NTOT x 64) for layer-1 self terms
                                 const float* __restrict__ bias,
                                 float* __restrict__ out,
                                 int applyRelu, int selfFull)
{
    int gw = (blockIdx.x * blockDim.x + threadIdx.x) >> 5;
    int lane = threadIdx.x & 31;
    if (gw >= Nn) return;
    int i = gw;
    float di0 = g_dinv[i];
    float di1 = g_dinv[Nn + i];
    float di2 = g_dinv[2*Nn + i];
    float di3 = g_dinv[3*Nn + i];
    float a0x=0.f,a0y=0.f,a1x=0.f,a1y=0.f,a2x=0.f,a2y=0.f,a3x=0.f,a3y=0.f;
    int beg = g_off[i], end = g_off[i+1];
    for (int k = beg; k < end; ++k) {
        int eid = g_eid[k];
        int s = srcArr[eid];
        unsigned m = g_mask[eid];
        float ad = g_dinv[s];
        float2 r = ((const float2*)(XW + (size_t)s*Ff))[lane];
        float c0 = ad * di0;
        a0x += r.x*c0; a0y += r.y*c0;
        if (m & 1u) { float c = ad*di1; a1x += r.x*c; a1y += r.y*c; }
        if (m & 2u) { float c = ad*di2; a2x += r.x*c; a2y += r.y*c; }
        if (m & 4u) { float c = ad*di3; a3x += r.x*c; a3y += r.y*c; }
    }
    float2 s0 = ((const float2*)(XW + (size_t)i*Ff))[lane];
    float2 bv = ((const float2*)bias)[lane];
    {   // replica 0: self-loop
        float c = di0*di0;
        float ox = a0x + s0.x*c + bv.x;
        float oy = a0y + s0.y*c + bv.y;
        if (applyRelu) { ox = fmaxf(ox, 0.f); oy = fmaxf(oy, 0.f); }
        ((float2*)(out + (size_t)i*Ff))[lane] = make_float2(ox, oy);
    }
#pragma unroll
    for (int t = 1; t <= 3; ++t) {
        float dit = (t==1) ? di1 : ((t==2) ? di2 : di3);
        float ax  = (t==1) ? a1x : ((t==2) ? a2x : a3x);
        float ay  = (t==1) ? a1y : ((t==2) ? a2y : a3y);
        float car = di0 * dit;                     // node->replica link edge (src = replica-0 node i)
        float2 selfrow = selfFull ? ((const float2*)(XWfull + ((size_t)t*Nn + i)*Ff))[lane] : s0;
        float cs = dit * dit;                      // self loop
        float ox = ax + s0.x*car + selfrow.x*cs + bv.x;
        float oy = ay + s0.y*car + selfrow.y*cs + bv.y;
        if (applyRelu) { ox = fmaxf(ox, 0.f); oy = fmaxf(oy, 0.f); }
        ((float2*)(out + ((size_t)t*Nn + i)*Ff))[lane] = make_float2(ox, oy);
    }
}

// ---------------- logits + argmax (warp per row) ----------------
__global__ void logits_kernel(const float* __restrict__ W, const float* __restrict__ b)
{
    __shared__ __align__(16) float WT[64][68];     // WT[j][k] = W[k][j]
    __shared__ float bs[64];
    __shared__ __align__(16) float hrow[8][64];
    int tid = threadIdx.x;
    for (int i = tid; i < 4096; i += 256) { int k = i >> 6, j = i & 63; WT[j][k] = W[i]; }
    if (tid < 64) bs[tid] = b[tid];
    __syncthreads();
    int wid = tid >> 5, lane = tid & 31;
    int row = blockIdx.x * 8 + wid;                // NTOT/8 = 25000 blocks exact
    float2 v = ((const float2*)(g_x2 + (size_t)row*64))[lane];
    hrow[wid][2*lane]   = fmaxf(v.x, 0.f);
    hrow[wid][2*lane+1] = fmaxf(v.y, 0.f);
    __syncwarp();
    float l0 = bs[lane], l1 = bs[lane + 32];
#pragma unroll
    for (int k = 0; k < 64; k += 4) {
        float4 h4 = *(const float4*)&hrow[wid][k];
        float4 wa = *(const float4*)&WT[lane][k];
        float4 wb = *(const float4*)&WT[lane + 32][k];
        l0 += h4.x*wa.x + h4.y*wa.y + h4.z*wa.z + h4.w*wa.w;
        l1 += h4.x*wb.x + h4.y*wb.y + h4.z*wb.z + h4.w*wb.w;
    }
    float bv; int bi;
    if (l0 >= l1) { bv = l0; bi = lane; } else { bv = l1; bi = lane + 32; }
#pragma unroll
    for (int o = 16; o; o >>= 1) {
        float ov = __shfl_xor_sync(0xffffffffu, bv, o);
        int   oi = __shfl_xor_sync(0xffffffffu, bi, o);
        if (ov > bv || (ov == bv && oi < bi)) { bv = ov; bi = oi; }
    }
    if (lane == 0) g_cls[row] = bi;
}

// ---------------- class aggregation: hyper + softmax column sums ----------------
__global__ void classagg_kernel()
{
    __shared__ float hy[NSs][Ff];                  // 16KB
    __shared__ float cs[NSs];
    int tid = threadIdx.x;
    for (int i = tid; i < NSs*Ff; i += 256) (&hy[0][0])[i] = 0.0f;
    if (tid < NSs) cs[tid] = 0.0f;
    __syncthreads();
    int wid = tid >> 5, lane = tid & 31;
    for (int n = blockIdx.x * 8 + wid; n < Nn; n += gridDim.x * 8) {
        int c0 = g_cls[n], c1 = g_cls[Nn + n], c2 = g_cls[2*Nn + n], c3 = g_cls[3*Nn + n];
        float2 x = ((const float2*)(g_x2 + (size_t)n*64))[lane];
#define PROC(c, cnt) { \
        atomicAdd(&hy[(c)][2*lane], x.x); atomicAdd(&hy[(c)][2*lane+1], x.y); \
        if (lane == 0) atomicAdd(&cs[(c)], expf((float)(cnt)) - 1.0f); }
        { int cnt = 1 + (c1==c0) + (c2==c0) + (c3==c0); PROC(c0, cnt); }
        if (c1 != c0)                         { int cnt = 1 + (c2==c1) + (c3==c1); PROC(c1, cnt); }
        if (c2 != c0 && c2 != c1)             { int cnt = 1 + (c3==c2);            PROC(c2, cnt); }
        if (c3 != c0 && c3 != c1 && c3 != c2) {                                    PROC(c3, 1);   }
#undef PROC
    }
    __syncthreads();
    for (int i = tid; i < NSs*Ff; i += 256) atomicAdd(&g_hyper[i], (&hy[0][0])[i]);
    if (tid < NSs) atomicAdd(&g_colsum[tid], cs[tid]);
}

// ---------------- H_soft output ----------------
__global__ void hsoft_kernel(float* __restrict__ outHs)
{
    __shared__ float inv[NSs];
    int tid = threadIdx.x;
    if (tid < NSs) inv[tid] = 1.0f / g_colsum[tid];
    __syncthreads();
    int wid = tid >> 5, lane = tid & 31;
    int n = blockIdx.x * 8 + wid;                  // 6250 blocks exact
    int c0 = g_cls[n], c1 = g_cls[Nn + n], c2 = g_cls[2*Nn + n], c3 = g_cls[3*Nn + n];
    float v0 = inv[2*lane], v1 = inv[2*lane + 1];
#define APPLY(c, cnt) { int cc = (c); if ((cc >> 1) == lane) { \
        float ev = expf((float)(cnt)) * inv[cc]; if (cc & 1) v1 = ev; else v0 = ev; } }
    { int cnt = 1 + (c1==c0) + (c2==c0) + (c3==c0); APPLY(c0, cnt); }
    if (c1 != c0)                         { int cnt = 1 + (c2==c1) + (c3==c1); APPLY(c1, cnt); }
    if (c2 != c0 && c2 != c1)             { int cnt = 1 + (c3==c2);            APPLY(c2, cnt); }
    if (c3 != c0 && c3 != c1 && c3 != c2) {                                    APPLY(c3, 1);   }
#undef APPLY
    ((float2*)(outHs + (size_t)n*64))[lane] = make_float2(v0, v1);
}

// ---------------- copy hyper to output ----------------
__global__ void copy_hyper(float* __restrict__ o)
{
    int i = blockIdx.x * blockDim.x + threadIdx.x;
    if (i < NSs*Ff) o[i] = g_hyper[i];
}

// ---------------- dots = features @ hyper^T * SCALE, written to all 4 replica blocks ----------------
__global__ void dots_kernel(const float* __restrict__ feat, float* __restrict__ outD)
{
    __shared__ __align__(16) float hyT[64][68];    // hyT[j][k] = hyper[j][k]
    __shared__ __align__(16) float frow[8][64];
    int tid = threadIdx.x;
    for (int i = tid; i < 4096; i += 256) hyT[i >> 6][i & 63] = g_hyper[i];
    __syncthreads();
    int wid = tid >> 5, lane = tid & 31;
    int n = blockIdx.x * 8 + wid;                  // 6250 blocks exact
    float2 v = ((const float2*)(feat + (size_t)n*64))[lane];
    frow[wid][2*lane] = v.x; frow[wid][2*lane+1] = v.y;
    __syncwarp();
    float l0 = 0.f, l1 = 0.f;
#pragma unroll
    for (int k = 0; k < 64; k += 4) {
        float4 h4 = *(const float4*)&frow[wid][k];
        float4 wa = *(const float4*)&hyT[lane][k];
        float4 wb = *(const float4*)&hyT[lane + 32][k];
        l0 += h4.x*wa.x + h4.y*wa.y + h4.z*wa.z + h4.w*wa.w;
        l1 += h4.x*wb.x + h4.y*wb.y + h4.z*wb.z + h4.w*wb.w;
    }
    const float SCALE = 0.125f;                    // 64^-0.5
    l0 *= SCALE; l1 *= SCALE;
#pragma unroll
    for (int rep = 0; rep < 4; rep++) {
        float* base = outD + ((size_t)rep*Nn + n)*64;
        base[lane] = l0;
        base[lane + 32] = l1;
    }
}

// ---------------- launcher ----------------
extern "C" void kernel_launch(void* const* d_in, const int* in_sizes, int n_in,
                              void* d_out, int out_size)
{
    (void)in_sizes; (void)n_in; (void)out_size;
    const int*   ei   = (const int*)d_in[0];
    const float* feat = (const float*)d_in[1];
    const float* Wlin = (const float*)d_in[2];
    const float* blin = (const float*)d_in[3];
    const float* g0W  = (const float*)d_in[4];
    const float* g0b  = (const float*)d_in[5];
    const float* g1W  = (const float*)d_in[6];
    const float* g1b  = (const float*)d_in[7];
    const float* l1W  = (const float*)d_in[8];
    const float* l1b  = (const float*)d_in[9];

    float* out   = (float*)d_out;
    float* outHs = out;                                    // (N, NS)
    float* outHy = out + (size_t)Nn*NSs;                   // (NS, F)
    float* outD  = out + (size_t)Nn*NSs + (size_t)NSs*Ff;  // (NTOT, NS)

    float *p_trans, *p_xw0, *p_h1, *p_xw1, *p_x2;
    cudaGetSymbolAddress((void**)&p_trans, g_trans);
    cudaGetSymbolAddress((void**)&p_xw0,   g_xw0);
    cudaGetSymbolAddress((void**)&p_h1,    g_h1);
    cudaGetSymbolAddress((void**)&p_xw1,   g_xw1);
    cudaGetSymbolAddress((void**)&p_x2,    g_x2);

    init_kernel<<<(Nn + 255)/256, 256>>>();

    // per-replica linear transforms
    for (int t = 0; t < Tt; t++)
        gemm64<<<(Nn + 63)/64, 256>>>(feat, Wlin + (size_t)t*Ff*Ff, blin + (size_t)t*Ff,
                                      p_trans + (size_t)t*Nn*Ff, Nn, 0);

    norms_kernel<<<(4*Nn*32 + 255)/256, 256>>>(feat);
    edge_kernel<<<(Ee*32)/256, 256>>>(ei, feat);
    scan_kernel<<<1, 1024>>>();
    fill_kernel<<<(Ee + 255)/256, 256>>>(ei);
    dinv_kernel<<<(Nn + 255)/256, 256>>>();

    // layer 0 (xw identical across replicas)
    gemm64<<<(Nn + 63)/64, 256>>>(feat, g0W, nullptr, p_xw0, Nn, 1);
    gcn_layer_kernel<<<(Nn + 7)/8, 256>>>(ei, p_xw0, p_xw0, g0b, p_h1, 1, 0);

    // layer 1
    gemm64<<<(NTOT + 63)/64, 256>>>(p_h1, g1W, nullptr, p_xw1, NTOT, 0);
    gcn_layer_kernel<<<(Nn + 7)/8, 256>>>(ei, p_xw1, p_xw1, g1b, p_x2, 0, 1);

    // logits + argmax
    logits_kernel<<<NTOT/8, 256>>>(l1W, l1b);

    // hyperedge features + softmax column sums
    classagg_kernel<<<128, 256>>>();

    // outputs
    hsoft_kernel<<<Nn/8, 256>>>(outHs);
    copy_hyper<<<16, 256>>>(outHy);
    dots_kernel<<<Nn/8, 256>>>(feat, outD);
}

// round 3
// speedup vs baseline: 1.4636x; 1.4636x over previous
#include <cuda_runtime.h>
#include <math.h>

#define Nn 50000
#define Ee 800000
#define Ff 64
#define Tt 3
#define NSs 64
#define NTOT (4*Nn)

// ---------------- scratch (device globals; no allocation allowed) ----------------
__device__ __align__(16) float g_trans[Tt*Nn*Ff];
__device__ float g_fnorm[Nn];
__device__ float g_tnorm[Tt*Nn];
__device__ unsigned char g_mask[Ee];
__device__ int g_indeg[Nn];
__device__ int g_off[Nn+1];
__device__ int g_fill[Nn];
__device__ int g_eid[Ee];              // packed: src | (mask<<16)
__device__ float g_dinv[4*Nn];
__device__ __align__(16) float g_xw0[Nn*Ff];
__device__ __align__(16) float g_h1[NTOT*Ff];
__device__ __align__(16) float g_xw1[NTOT*Ff];
__device__ __align__(16) float g_x2[NTOT*Ff];
__device__ int g_cls[NTOT];
__device__ __align__(16) float g_hyper[NSs*Ff];
__device__ float g_colsum[NSs];

// ---------------- init ----------------
__global__ void init_kernel()
{
    int i = blockIdx.x * blockDim.x + threadIdx.x;
    if (i < Nn) { g_indeg[i] = 0; g_fill[i] = 0; }
    if (i < NSs*Ff) g_hyper[i] = 0.0f;
    if (i < NSs) g_colsum[i] = (float)Nn;
}

// ---------------- register-blocked GEMM: out = (relu?)X @ W (+bias), K=N=64 ----------------
// BM=128 rows/block, 128 threads, 8x8 micro-tile. blockIdx.y = weight batch.
__global__ __launch_bounds__(128)
void gemm_rb(const float* __restrict__ X, const float* __restrict__ W,
             const float* __restrict__ bias, float* __restrict__ out,
             int rows, int relu_in, float* __restrict__ normOut)
{
    __shared__ float As[128*64];   // 32KB
    __shared__ float Bs[64*64];    // 16KB  (total 48KB exactly)
    const int tid = threadIdx.x;
    const int tx = tid & 7;        // 8 col-groups of 8
    const int ty = tid >> 3;       // 16 row-groups of 8
    const int b  = blockIdx.y;
    const int row0 = blockIdx.x * 128;

    const float* Wb = W + (size_t)b * 4096;

    // load A tile (relu optional, zero-pad OOB rows)
#pragma unroll
    for (int it = 0; it < 16; it++) {
        int idx = tid + it * 128;
        int r = idx >> 4, c4 = (idx & 15) << 2;
        int gr = row0 + r;
        float4 v = make_float4(0.f, 0.f, 0.f, 0.f);
        if (gr < rows) v = *(const float4*)&X[(size_t)gr*64 + c4];
        if (relu_in) { v.x = fmaxf(v.x,0.f); v.y = fmaxf(v.y,0.f); v.z = fmaxf(v.z,0.f); v.w = fmaxf(v.w,0.f); }
        *(float4*)&As[r*64 + c4] = v;
    }
    // load B (W row-major, 64x64)
#pragma unroll
    for (int it = 0; it < 8; it++) {
        int idx = tid + it * 128;
        int k = idx >> 4, c4 = (idx & 15) << 2;
        *(float4*)&Bs[k*64 + c4] = *(const float4*)&Wb[k*64 + c4];
    }
    __syncthreads();

    float acc[8][8];
#pragma unroll
    for (int i = 0; i < 8; i++)
#pragma unroll
        for (int j = 0; j < 8; j++) acc[i][j] = 0.f;

    const int rbase = ty * 8;
    const int c0 = tx * 8;
#pragma unroll
    for (int k0 = 0; k0 < 64; k0 += 4) {
        float4 a[8];
#pragma unroll
        for (int i = 0; i < 8; i++) a[i] = *(const float4*)&As[(rbase+i)*64 + k0];
#pragma unroll
        for (int kk = 0; kk < 4; kk++) {
            float4 b0 = *(const float4*)&Bs[(k0+kk)*64 + c0];
            float4 b1 = *(const float4*)&Bs[(k0+kk)*64 + c0 + 4];
            float bb[8] = {b0.x,b0.y,b0.z,b0.w,b1.x,b1.y,b1.z,b1.w};
#pragma unroll
            for (int i = 0; i < 8; i++) {
                float av = (kk==0) ? a[i].x : (kk==1) ? a[i].y : (kk==2) ? a[i].z : a[i].w;
#pragma unroll
                for (int j = 0; j < 8; j++) acc[i][j] += av * bb[j];
            }
        }
    }

    float bj[8];
#pragma unroll
    for (int j = 0; j < 8; j++) bj[j] = bias ? bias[(size_t)b*64 + c0 + j] : 0.f;

    float* outb = out + (size_t)b * rows * 64;
#pragma unroll
    for (int i = 0; i < 8; i++) {
        int gr = row0 + rbase + i;
        float v[8];
        float sq = 0.f;
#pragma unroll
        for (int j = 0; j < 8; j++) { v[j] = acc[i][j] + bj[j]; sq += v[j]*v[j]; }
        if (gr < rows) {
            *(float4*)&outb[(size_t)gr*64 + c0]     = make_float4(v[0],v[1],v[2],v[3]);
            *(float4*)&outb[(size_t)gr*64 + c0 + 4] = make_float4(v[4],v[5],v[6],v[7]);
        }
        if (normOut) {
            // reduce sq across the 8 tx lanes (same ty group sits in consecutive lanes)
            sq += __shfl_xor_sync(0xffffffffu, sq, 1);
            sq += __shfl_xor_sync(0xffffffffu, sq, 2);
            sq += __shfl_xor_sync(0xffffffffu, sq, 4);
            if (tx == 0 && gr < rows)
                normOut[(size_t)b*rows + gr] = fmaxf(sqrtf(sq), 1e-8f);
        }
    }
}

// ---------------- feature row norms ----------------
__global__ void norms_kernel(const float* __restrict__ feat)
{
    int w = (blockIdx.x * blockDim.x + threadIdx.x) >> 5;
    int lane = threadIdx.x & 31;
    if (w >= Nn) return;
    float2 v = ((const float2*)(feat + (size_t)w*64))[lane];
    float s = v.x*v.x + v.y*v.y;
#pragma unroll
    for (int o = 16; o; o >>= 1) s += __shfl_xor_sync(0xffffffffu, s, o);
    if (lane == 0) g_fnorm[w] = fmaxf(sqrtf(s), 1e-8f);
}

// ---------------- per-edge cosine sims -> masks; indegree count ----------------
__global__ void edge_kernel(const int* __restrict__ ei, const float* __restrict__ feat)
{
    int w = (blockIdx.x * blockDim.x + threadIdx.x) >> 5;
    int lane = threadIdx.x & 31;
    if (w >= Ee) return;
    int s = ei[w], d = ei[Ee + w];
    float2 a  = ((const float2*)(feat + (size_t)s*64))[lane];
    float2 b  = ((const float2*)(feat + (size_t)d*64))[lane];
    float2 t0 = ((const float2*)(g_trans + (size_t)s*64))[lane];
    float2 t1 = ((const float2*)(g_trans + (size_t)(Nn + s)*64))[lane];
    float2 t2 = ((const float2*)(g_trans + (size_t)(2*Nn + s)*64))[lane];
    float d0 = a.x*b.x + a.y*b.y;
    float e0 = t0.x*b.x + t0.y*b.y;
    float e1 = t1.x*b.x + t1.y*b.y;
    float e2 = t2.x*b.x + t2.y*b.y;
#pragma unroll
    for (int o = 16; o; o >>= 1) {
        d0 += __shfl_xor_sync(0xffffffffu, d0, o);
        e0 += __shfl_xor_sync(0xffffffffu, e0, o);
        e1 += __shfl_xor_sync(0xffffffffu, e1, o);
        e2 += __shfl_xor_sync(0xffffffffu, e2, o);
    }
    if (lane == 0) {
        float ns = g_fnorm[s], nd = g_fnorm[d];
        float sim0 = d0 / (ns * nd);
        unsigned m = 0;
        if (e0 / (g_tnorm[s]        * nd) > sim0) m |= 1u;
        if (e1 / (g_tnorm[Nn + s]   * nd) > sim0) m |= 2u;
        if (e2 / (g_tnorm[2*Nn + s] * nd) > sim0) m |= 4u;
        g_mask[w] = (unsigned char)m;
        atomicAdd(&g_indeg[d], 1);
    }
}

// ---------------- exclusive scan of indeg (single block, warp-shuffle) ----------------
__global__ void scan_kernel()
{
    __shared__ int wsum[32];
    __shared__ int tileTotal;
    __shared__ int carry_s;
    int tid = threadIdx.x, lane = tid & 31, wid = tid >> 5;
    if (tid == 0) carry_s = 0;
    __syncthreads();
    for (int base = 0; base < Nn; base += 4096) {
        int idx4 = base + tid * 4;
        int4 v = make_int4(0,0,0,0);
        if (idx4 + 3 < Nn) v = *(const int4*)&g_indeg[idx4];
        else if (idx4 < Nn) {
            v.x = g_indeg[idx4];
            if (idx4+1 < Nn) v.y = g_indeg[idx4+1];
            if (idx4+2 < Nn) v.z = g_indeg[idx4+2];
        }
        int local = v.x + v.y + v.z + v.w;
        int incl = local;
#pragma unroll
        for (int o = 1; o < 32; o <<= 1) {
            int t = __shfl_up_sync(0xffffffffu, incl, o);
            if (lane >= o) incl += t;
        }
        if (lane == 31) wsum[wid] = incl;
        __syncthreads();
        if (wid == 0) {
            int s = wsum[lane];
            int si = s;
#pragma unroll
            for (int o = 1; o < 32; o <<= 1) {
                int t = __shfl_up_sync(0xffffffffu, si, o);
                if (lane >= o) si += t;
            }
            wsum[lane] = si - s;
            if (lane == 31) tileTotal = si;
        }
        __syncthreads();
        int excl = carry_s + wsum[wid] + (incl - local);
        if (idx4 + 3 < Nn) {
            *(int4*)&g_off[idx4] = make_int4(excl, excl+v.x, excl+v.x+v.y, excl+v.x+v.y+v.z);
        } else if (idx4 < Nn) {
            g_off[idx4] = excl;
            if (idx4+1 < Nn) g_off[idx4+1] = excl + v.x;
            if (idx4+2 < Nn) g_off[idx4+2] = excl + v.x + v.y;
        }
        __syncthreads();
        if (tid == 0) carry_s += tileTotal;
        __syncthreads();
    }
    if (tid == 0) g_off[Nn] = carry_s;
}

// ---------------- CSR fill (packed src|mask) ----------------
__global__ void fill_kernel(const int* __restrict__ ei)
{
    int e = blockIdx.x * blockDim.x + threadIdx.x;
    if (e >= Ee) return;
    int s = ei[e];
    int d = ei[Ee + e];
    unsigned m = g_mask[e];
    int p = g_off[d] + atomicAdd(&g_fill[d], 1);
    g_eid[p] = s | ((int)m << 16);
}

// ---------------- degrees -> dinv per replica ----------------
__global__ void dinv_kernel()
{
    int i = blockIdx.x * blockDim.x + threadIdx.x;
    if (i >= Nn) return;
    int beg = g_off[i], end = g_off[i+1];
    int c1 = 0, c2 = 0, c3 = 0;
    for (int k = beg; k < end; k++) {
        unsigned m = (unsigned)g_eid[k] >> 16;
        c1 += (m)      & 1u;
        c2 += (m >> 1) & 1u;
        c3 += (m >> 2) & 1u;
    }
    g_dinv[i]        = 1.0f / sqrtf((float)(end - beg) + 1.0f);
    g_dinv[Nn + i]   = 1.0f / sqrtf((float)c1 + 2.0f);
    g_dinv[2*Nn + i] = 1.0f / sqrtf((float)c2 + 2.0f);
    g_dinv[3*Nn + i] = 1.0f / sqrtf((float)c3 + 2.0f);
}

// ---------------- GCN layer: gather-side reduction, warp per node, 4 replicas fused ----------------
__global__ void gcn_layer_kernel(const float* __restrict__ XW,      // replica-0 gather source (N x 64)
                                 const float* __restrict__ XWfull,  // full (NTOT x 64) for layer-1 self terms
                                 const float* __restrict__ bias,
                                 float* __restrict__ out,
                                 int applyRelu, int selfFull)
{
    int gw = (blockIdx.x * blockDim.x + threadIdx.x) >> 5;
    int lane = threadIdx.x & 31;
    if (gw >= Nn) return;
    int i = gw;
    float di0 = g_dinv[i];
    float di1 = g_dinv[Nn + i];
    float di2 = g_dinv[2*Nn + i];
    float di3 = g_dinv[3*Nn + i];
    float a0x=0.f,a0y=0.f,a1x=0.f,a1y=0.f,a2x=0.f,a2y=0.f,a3x=0.f,a3y=0.f;
    int beg = g_off[i], end = g_off[i+1];
    for (int k = beg; k < end; ++k) {
        int p = g_eid[k];
        int s = p & 0xFFFF;
        unsigned m = (unsigned)p >> 16;
        float ad = g_dinv[s];
        float2 r = ((const float2*)(XW + (size_t)s*Ff))[lane];
        float c0 = ad * di0;
        a0x += r.x*c0; a0y += r.y*c0;
        if (m & 1u) { float c = ad*di1; a1x += r.x*c; a1y += r.y*c; }
        if (m & 2u) { float c = ad*di2; a2x += r.x*c; a2y += r.y*c; }
        if (m & 4u) { float c = ad*di3; a3x += r.x*c; a3y += r.y*c; }
    }
    float2 s0 = ((const float2*)(XW + (size_t)i*Ff))[lane];
    float2 bv = ((const float2*)bias)[lane];
    {   // replica 0: self-loop
        float c = di0*di0;
        float ox = a0x + s0.x*c + bv.x;
        float oy = a0y + s0.y*c + bv.y;
        if (applyRelu) { ox = fmaxf(ox, 0.f); oy = fmaxf(oy, 0.f); }
        ((float2*)(out + (size_t)i*Ff))[lane] = make_float2(ox, oy);
    }
#pragma unroll
    for (int t = 1; t <= 3; ++t) {
        float dit = (t==1) ? di1 : ((t==2) ? di2 : di3);
        float ax  = (t==1) ? a1x : ((t==2) ? a2x : a3x);
        float ay  = (t==1) ? a1y : ((t==2) ? a2y : a3y);
        float car = di0 * dit;                     // node->replica link edge (src = replica-0 node i)
        float2 selfrow = selfFull ? ((const float2*)(XWfull + ((size_t)t*Nn + i)*Ff))[lane] : s0;
        float cs = dit * dit;                      // self loop
        float ox = ax + s0.x*car + selfrow.x*cs + bv.x;
        float oy = ay + s0.y*car + selfrow.y*cs + bv.y;
        if (applyRelu) { ox = fmaxf(ox, 0.f); oy = fmaxf(oy, 0.f); }
        ((float2*)(out + ((size_t)t*Nn + i)*Ff))[lane] = make_float2(ox, oy);
    }
}

// ---------------- logits + argmax (warp per row) ----------------
__global__ void logits_kernel(const float* __restrict__ W, const float* __restrict__ b)
{
    __shared__ __align__(16) float WT[64][68];     // WT[j][k] = W[k][j]
    __shared__ float bs[64];
    __shared__ __align__(16) float hrow[8][64];
    int tid = threadIdx.x;
    for (int i = tid; i < 4096; i += 256) { int k = i >> 6, j = i & 63; WT[j][k] = W[i]; }
    if (tid < 64) bs[tid] = b[tid];
    __syncthreads();
    int wid = tid >> 5, lane = tid & 31;
    int row = blockIdx.x * 8 + wid;                // NTOT/8 = 25000 blocks exact
    float2 v = ((const float2*)(g_x2 + (size_t)row*64))[lane];
    hrow[wid][2*lane]   = fmaxf(v.x, 0.f);
    hrow[wid][2*lane+1] = fmaxf(v.y, 0.f);
    __syncwarp();
    float l0 = bs[lane], l1 = bs[lane + 32];
#pragma unroll
    for (int k = 0; k < 64; k += 4) {
        float4 h4 = *(const float4*)&hrow[wid][k];
        float4 wa = *(const float4*)&WT[lane][k];
        float4 wb = *(const float4*)&WT[lane + 32][k];
        l0 += h4.x*wa.x + h4.y*wa.y + h4.z*wa.z + h4.w*wa.w;
        l1 += h4.x*wb.x + h4.y*wb.y + h4.z*wb.z + h4.w*wb.w;
    }
    float bv; int bi;
    if (l0 >= l1) { bv = l0; bi = lane; } else { bv = l1; bi = lane + 32; }
#pragma unroll
    for (int o = 16; o; o >>= 1) {
        float ov = __shfl_xor_sync(0xffffffffu, bv, o);
        int   oi = __shfl_xor_sync(0xffffffffu, bi, o);
        if (ov > bv || (ov == bv && oi < bi)) { bv = ov; bi = oi; }
    }
    if (lane == 0) g_cls[row] = bi;
}

// ---------------- class aggregation: hyper + softmax column sums ----------------
__global__ void classagg_kernel()
{
    __shared__ float hy[NSs][Ff];                  // 16KB
    __shared__ float cs[NSs];
    int tid = threadIdx.x;
    for (int i = tid; i < NSs*Ff; i += 256) (&hy[0][0])[i] = 0.0f;
    if (tid < NSs) cs[tid] = 0.0f;
    __syncthreads();
    int wid = tid >> 5, lane = tid & 31;
    for (int n = blockIdx.x * 8 + wid; n < Nn; n += gridDim.x * 8) {
        int c0 = g_cls[n], c1 = g_cls[Nn + n], c2 = g_cls[2*Nn + n], c3 = g_cls[3*Nn + n];
        float2 x = ((const float2*)(g_x2 + (size_t)n*64))[lane];
#define PROC(c, cnt) { \
        atomicAdd(&hy[(c)][2*lane], x.x); atomicAdd(&hy[(c)][2*lane+1], x.y); \
        if (lane == 0) atomicAdd(&cs[(c)], expf((float)(cnt)) - 1.0f); }
        { int cnt = 1 + (c1==c0) + (c2==c0) + (c3==c0); PROC(c0, cnt); }
        if (c1 != c0)                         { int cnt = 1 + (c2==c1) + (c3==c1); PROC(c1, cnt); }
        if (c2 != c0 && c2 != c1)             { int cnt = 1 + (c3==c2);            PROC(c2, cnt); }
        if (c3 != c0 && c3 != c1 && c3 != c2) {                                    PROC(c3, 1);   }
#undef PROC
    }
    __syncthreads();
    for (int i = tid; i < NSs*Ff; i += 256) atomicAdd(&g_hyper[i], (&hy[0][0])[i]);
    if (tid < NSs) atomicAdd(&g_colsum[tid], cs[tid]);
}

// ---------------- H_soft output ----------------
__global__ void hsoft_kernel(float* __restrict__ outHs)
{
    __shared__ float inv[NSs];
    int tid = threadIdx.x;
    if (tid < NSs) inv[tid] = 1.0f / g_colsum[tid];
    __syncthreads();
    int wid = tid >> 5, lane = tid & 31;
    int n = blockIdx.x * 8 + wid;                  // 6250 blocks exact
    int c0 = g_cls[n], c1 = g_cls[Nn + n], c2 = g_cls[2*Nn + n], c3 = g_cls[3*Nn + n];
    float v0 = inv[2*lane], v1 = inv[2*lane + 1];
#define APPLY(c, cnt) { int cc = (c); if ((cc >> 1) == lane) { \
        float ev = expf((float)(cnt)) * inv[cc]; if (cc & 1) v1 = ev; else v0 = ev; } }
    { int cnt = 1 + (c1==c0) + (c2==c0) + (c3==c0); APPLY(c0, cnt); }
    if (c1 != c0)                         { int cnt = 1 + (c2==c1) + (c3==c1); APPLY(c1, cnt); }
    if (c2 != c0 && c2 != c1)             { int cnt = 1 + (c3==c2);            APPLY(c2, cnt); }
    if (c3 != c0 && c3 != c1 && c3 != c2) {                                    APPLY(c3, 1);   }
#undef APPLY
    ((float2*)(outHs + (size_t)n*64))[lane] = make_float2(v0, v1);
}

// ---------------- copy hyper to output ----------------
__global__ void copy_hyper(float* __restrict__ o)
{
    int i = blockIdx.x * blockDim.x + threadIdx.x;
    if (i < NSs*Ff) o[i] = g_hyper[i];
}

// ---------------- dots = features @ hyper^T * SCALE, written to all 4 replica blocks ----------------
__global__ void dots_kernel(const float* __restrict__ feat, float* __restrict__ outD)
{
    __shared__ __align__(16) float hyT[64][68];    // hyT[j][k] = hyper[j][k]
    __shared__ __align__(16) float frow[8][64];
    int tid = threadIdx.x;
    for (int i = tid; i < 4096; i += 256) hyT[i >> 6][i & 63] = g_hyper[i];
    __syncthreads();
    int wid = tid >> 5, lane = tid & 31;
    int n = blockIdx.x * 8 + wid;                  // 6250 blocks exact
    float2 v = ((const float2*)(feat + (size_t)n*64))[lane];
    frow[wid][2*lane] = v.x; frow[wid][2*lane+1] = v.y;
    __syncwarp();
    float l0 = 0.f, l1 = 0.f;
#pragma unroll
    for (int k = 0; k < 64; k += 4) {
        float4 h4 = *(const float4*)&frow[wid][k];
        float4 wa = *(const float4*)&hyT[lane][k];
        float4 wb = *(const float4*)&hyT[lane + 32][k];
        l0 += h4.x*wa.x + h4.y*wa.y + h4.z*wa.z + h4.w*wa.w;
        l1 += h4.x*wb.x + h4.y*wb.y + h4.z*wb.z + h4.w*wb.w;
    }
    const float SCALE = 0.125f;                    // 64^-0.5
    l0 *= SCALE; l1 *= SCALE;
#pragma unroll
    for (int rep = 0; rep < 4; rep++) {
        float* base = outD + ((size_t)rep*Nn + n)*64;
        base[lane] = l0;
        base[lane + 32] = l1;
    }
}

// ---------------- launcher ----------------
extern "C" void kernel_launch(void* const* d_in, const int* in_sizes, int n_in,
                              void* d_out, int out_size)
{
    (void)in_sizes; (void)n_in; (void)out_size;
    const int*   ei   = (const int*)d_in[0];
    const float* feat = (const float*)d_in[1];
    const float* Wlin = (const float*)d_in[2];
    const float* blin = (const float*)d_in[3];
    const float* g0W  = (const float*)d_in[4];
    const float* g0b  = (const float*)d_in[5];
    const float* g1W  = (const float*)d_in[6];
    const float* g1b  = (const float*)d_in[7];
    const float* l1W  = (const float*)d_in[8];
    const float* l1b  = (const float*)d_in[9];

    float* out   = (float*)d_out;
    float* outHs = out;                                    // (N, NS)
    float* outHy = out + (size_t)Nn*NSs;                   // (NS, F)
    float* outD  = out + (size_t)Nn*NSs + (size_t)NSs*Ff;  // (NTOT, NS)

    float *p_trans, *p_xw0, *p_h1, *p_xw1, *p_x2, *p_tnorm;
    cudaGetSymbolAddress((void**)&p_trans, g_trans);
    cudaGetSymbolAddress((void**)&p_xw0,   g_xw0);
    cudaGetSymbolAddress((void**)&p_h1,    g_h1);
    cudaGetSymbolAddress((void**)&p_xw1,   g_xw1);
    cudaGetSymbolAddress((void**)&p_x2,    g_x2);
    cudaGetSymbolAddress((void**)&p_tnorm, g_tnorm);

    init_kernel<<<(Nn + 255)/256, 256>>>();

    const int GB_N    = (Nn + 127) / 128;     // 391
    const int GB_NTOT = (NTOT + 127) / 128;   // 1563

    // per-replica linear transforms (batched) + fused trans-norms
    gemm_rb<<<dim3(GB_N, 3), 128>>>(feat, Wlin, blin, p_trans, Nn, 0, p_tnorm);

    norms_kernel<<<(Nn*32 + 255)/256, 256>>>(feat);
    edge_kernel<<<(Ee*32)/256, 256>>>(ei, feat);
    scan_kernel<<<1, 1024>>>();
    fill_kernel<<<(Ee + 255)/256, 256>>>(ei);
    dinv_kernel<<<(Nn + 255)/256, 256>>>();

    // layer 0 (xw identical across replicas)
    gemm_rb<<<dim3(GB_N, 1), 128>>>(feat, g0W, nullptr, p_xw0, Nn, 1, nullptr);
    gcn_layer_kernel<<<(Nn + 7)/8, 256>>>(p_xw0, p_xw0, g0b, p_h1, 1, 0);

    // layer 1
    gemm_rb<<<dim3(GB_NTOT, 1), 128>>>(p_h1, g1W, nullptr, p_xw1, NTOT, 0, nullptr);
    gcn_layer_kernel<<<(Nn + 7)/8, 256>>>(p_xw1, p_xw1, g1b, p_x2, 0, 1);

    // logits + argmax
    logits_kernel<<<NTOT/8, 256>>>(l1W, l1b);

    // hyperedge features + softmax column sums
    classagg_kernel<<<128, 256>>>();

    // outputs
    hsoft_kernel<<<Nn/8, 256>>>(outHs);
    copy_hyper<<<16, 256>>>(outHy);
    dots_kernel<<<Nn/8, 256>>>(feat, outD);
}

// round 4
// speedup vs baseline: 1.9767x; 1.3506x over previous
#include <cuda_runtime.h>
#include <math.h>

#define Nn 50000
#define Ee 800000
#define Ff 64
#define Tt 3
#define NSs 64
#define NTOT (4*Nn)

// ---------------- scratch (device globals; no allocation allowed) ----------------
__device__ __align__(16) float g_diff[Nn*192];   // per node: 3 normalized-difference rows
__device__ unsigned char g_mask[Ee];
__device__ int g_indeg[Nn];
__device__ int g_cnt3[Nn];                        // packed replica counts (10 bits each)
__device__ int g_off[Nn+1];
__device__ int g_fill[Nn];
__device__ int g_eid[Ee];                         // packed: src | (mask<<16)
__device__ float g_dinv[4*Nn];
__device__ __align__(16) float g_xw0[Nn*Ff];
__device__ __align__(16) float g_h1[NTOT*Ff];
__device__ __align__(16) float g_xw1[NTOT*Ff];
__device__ __align__(16) float g_x2[NTOT*Ff];
__device__ int g_cls[NTOT];
__device__ __align__(16) float g_hyper[NSs*Ff];
__device__ float g_colsum[NSs];

// ---------------- init ----------------
__global__ void init_kernel()
{
    int i = blockIdx.x * blockDim.x + threadIdx.x;
    if (i < Nn) { g_indeg[i] = 0; g_fill[i] = 0; g_cnt3[i] = 0; }
    if (i < NSs*Ff) g_hyper[i] = 0.0f;
    if (i < NSs) g_colsum[i] = (float)Nn;
}

// ---------------- register-blocked GEMM: out = (relu?)X @ W (+bias), K=N=64 ----------------
// BM=128 rows/block, 128 threads, 8x8 micro-tile. blockIdx.y = weight batch.
// If diffMode: instead of writing the GEMM result, write the normalized-difference
// rows  diff = v/max(|v|,eps) - x/max(|x|,eps)  to g_diff[row*192 + b*64 + ...].
__global__ __launch_bounds__(128)
void gemm_rb(const float* __restrict__ X, const float* __restrict__ W,
             const float* __restrict__ bias, float* __restrict__ out,
             int rows, int relu_in, int diffMode)
{
    __shared__ float As[128*64];   // 32KB
    __shared__ float Bs[64*64];    // 16KB
    const int tid = threadIdx.x;
    const int tx = tid & 7;
    const int ty = tid >> 3;
    const int b  = blockIdx.y;
    const int row0 = blockIdx.x * 128;

    const float* Wb = W + (size_t)b * 4096;

#pragma unroll
    for (int it = 0; it < 16; it++) {
        int idx = tid + it * 128;
        int r = idx >> 4, c4 = (idx & 15) << 2;
        int gr = row0 + r;
        float4 v = make_float4(0.f, 0.f, 0.f, 0.f);
        if (gr < rows) v = *(const float4*)&X[(size_t)gr*64 + c4];
        if (relu_in) { v.x = fmaxf(v.x,0.f); v.y = fmaxf(v.y,0.f); v.z = fmaxf(v.z,0.f); v.w = fmaxf(v.w,0.f); }
        *(float4*)&As[r*64 + c4] = v;
    }
#pragma unroll
    for (int it = 0; it < 8; it++) {
        int idx = tid + it * 128;
        int k = idx >> 4, c4 = (idx & 15) << 2;
        *(float4*)&Bs[k*64 + c4] = *(const float4*)&Wb[k*64 + c4];
    }
    __syncthreads();

    float acc[8][8];
#pragma unroll
    for (int i = 0; i < 8; i++)
#pragma unroll
        for (int j = 0; j < 8; j++) acc[i][j] = 0.f;

    const int rbase = ty * 8;
    const int c0 = tx * 8;
#pragma unroll
    for (int k0 = 0; k0 < 64; k0 += 4) {
        float4 a[8];
#pragma unroll
        for (int i = 0; i < 8; i++) a[i] = *(const float4*)&As[(rbase+i)*64 + k0];
#pragma unroll
        for (int kk = 0; kk < 4; kk++) {
            float4 b0 = *(const float4*)&Bs[(k0+kk)*64 + c0];
            float4 b1 = *(const float4*)&Bs[(k0+kk)*64 + c0 + 4];
            float bb[8] = {b0.x,b0.y,b0.z,b0.w,b1.x,b1.y,b1.z,b1.w};
#pragma unroll
            for (int i = 0; i < 8; i++) {
                float av = (kk==0) ? a[i].x : (kk==1) ? a[i].y : (kk==2) ? a[i].z : a[i].w;
#pragma unroll
                for (int j = 0; j < 8; j++) acc[i][j] += av * bb[j];
            }
        }
    }

    float bj[8];
#pragma unroll
    for (int j = 0; j < 8; j++) bj[j] = bias ? bias[(size_t)b*64 + c0 + j] : 0.f;

    if (!diffMode) {
        float* outb = out + (size_t)b * rows * 64;
#pragma unroll
        for (int i = 0; i < 8; i++) {
            int gr = row0 + rbase + i;
            if (gr >= rows) continue;
            float v[8];
#pragma unroll
            for (int j = 0; j < 8; j++) v[j] = acc[i][j] + bj[j];
            *(float4*)&outb[(size_t)gr*64 + c0]     = make_float4(v[0],v[1],v[2],v[3]);
            *(float4*)&outb[(size_t)gr*64 + c0 + 4] = make_float4(v[4],v[5],v[6],v[7]);
        }
    } else {
#pragma unroll
        for (int i = 0; i < 8; i++) {
            int gr = row0 + rbase + i;
            float v[8], x[8];
            float sqv = 0.f, sqx = 0.f;
#pragma unroll
            for (int j = 0; j < 8; j++) {
                v[j] = acc[i][j] + bj[j];
                x[j] = As[(rbase+i)*64 + c0 + j];
                sqv += v[j]*v[j];
                sqx += x[j]*x[j];
            }
            // reduce over the 8 tx lanes (consecutive lanes share ty)
            sqv += __shfl_xor_sync(0xffffffffu, sqv, 1);
            sqv += __shfl_xor_sync(0xffffffffu, sqv, 2);
            sqv += __shfl_xor_sync(0xffffffffu, sqv, 4);
            sqx += __shfl_xor_sync(0xffffffffu, sqx, 1);
            sqx += __shfl_xor_sync(0xffffffffu, sqx, 2);
            sqx += __shfl_xor_sync(0xffffffffu, sqx, 4);
            float itn = 1.0f / fmaxf(sqrtf(sqv), 1e-8f);
            float ixn = 1.0f / fmaxf(sqrtf(sqx), 1e-8f);
            if (gr < rows) {
                float d[8];
#pragma unroll
                for (int j = 0; j < 8; j++) d[j] = v[j]*itn - x[j]*ixn;
                float* dst = &g_diff[(size_t)gr*192 + b*64 + c0];
                *(float4*)&dst[0] = make_float4(d[0],d[1],d[2],d[3]);
                *(float4*)&dst[4] = make_float4(d[4],d[5],d[6],d[7]);
            }
        }
    }
}

// ---------------- per-edge masks via difference rows; 16 lanes per edge ----------------
__global__ void edge_kernel(const int* __restrict__ ei, const float* __restrict__ feat)
{
    int gid = blockIdx.x * blockDim.x + threadIdx.x;
    int e = gid >> 4;
    int q = threadIdx.x & 15;
    if (e >= Ee) return;
    int s = ei[e], d = ei[Ee + e];
    float4 fd = ((const float4*)(feat + (size_t)d*64))[q];
    const float4* dp = (const float4*)(g_diff + (size_t)s*192);
    float4 r0 = dp[q], r1 = dp[16 + q], r2 = dp[32 + q];
    float p0 = r0.x*fd.x + r0.y*fd.y + r0.z*fd.z + r0.w*fd.w;
    float p1 = r1.x*fd.x + r1.y*fd.y + r1.z*fd.z + r1.w*fd.w;
    float p2 = r2.x*fd.x + r2.y*fd.y + r2.z*fd.z + r2.w*fd.w;
#pragma unroll
    for (int o = 8; o; o >>= 1) {
        p0 += __shfl_xor_sync(0xffffffffu, p0, o);
        p1 += __shfl_xor_sync(0xffffffffu, p1, o);
        p2 += __shfl_xor_sync(0xffffffffu, p2, o);
    }
    if (q == 0) {
        unsigned m = 0;
        int pk = 0;
        if (p0 > 0.f) { m |= 1u; pk += 1; }
        if (p1 > 0.f) { m |= 2u; pk += 1 << 10; }
        if (p2 > 0.f) { m |= 4u; pk += 1 << 20; }
        g_mask[e] = (unsigned char)m;
        atomicAdd(&g_indeg[d], 1);
        if (pk) atomicAdd(&g_cnt3[d], pk);
    }
}

// ---------------- exclusive scan of indeg (single block, warp-shuffle) ----------------
__global__ void scan_kernel()
{
    __shared__ int wsum[32];
    __shared__ int tileTotal;
    __shared__ int carry_s;
    int tid = threadIdx.x, lane = tid & 31, wid = tid >> 5;
    if (tid == 0) carry_s = 0;
    __syncthreads();
    for (int base = 0; base < Nn; base += 4096) {
        int idx4 = base + tid * 4;
        int4 v = make_int4(0,0,0,0);
        if (idx4 + 3 < Nn) v = *(const int4*)&g_indeg[idx4];
        else if (idx4 < Nn) {
            v.x = g_indeg[idx4];
            if (idx4+1 < Nn) v.y = g_indeg[idx4+1];
            if (idx4+2 < Nn) v.z = g_indeg[idx4+2];
        }
        int local = v.x + v.y + v.z + v.w;
        int incl = local;
#pragma unroll
        for (int o = 1; o < 32; o <<= 1) {
            int t = __shfl_up_sync(0xffffffffu, incl, o);
            if (lane >= o) incl += t;
        }
        if (lane == 31) wsum[wid] = incl;
        __syncthreads();
        if (wid == 0) {
            int s = wsum[lane];
            int si = s;
#pragma unroll
            for (int o = 1; o < 32; o <<= 1) {
                int t = __shfl_up_sync(0xffffffffu, si, o);
                if (lane >= o) si += t;
            }
            wsum[lane] = si - s;
            if (lane == 31) tileTotal = si;
        }
        __syncthreads();
        int excl = carry_s + wsum[wid] + (incl - local);
        if (idx4 + 3 < Nn) {
            *(int4*)&g_off[idx4] = make_int4(excl, excl+v.x, excl+v.x+v.y, excl+v.x+v.y+v.z);
        } else if (idx4 < Nn) {
            g_off[idx4] = excl;
            if (idx4+1 < Nn) g_off[idx4+1] = excl + v.x;
            if (idx4+2 < Nn) g_off[idx4+2] = excl + v.x + v.y;
        }
        __syncthreads();
        if (tid == 0) carry_s += tileTotal;
        __syncthreads();
    }
    if (tid == 0) g_off[Nn] = carry_s;
}

// ---------------- CSR fill (packed src|mask) ----------------
__global__ void fill_kernel(const int* __restrict__ ei)
{
    int e = blockIdx.x * blockDim.x + threadIdx.x;
    if (e >= Ee) return;
    int s = ei[e];
    int d = ei[Ee + e];
    unsigned m = g_mask[e];
    int p = g_off[d] + atomicAdd(&g_fill[d], 1);
    g_eid[p] = s | ((int)m << 16);
}

// ---------------- degrees -> dinv per replica (elementwise) ----------------
__global__ void dinv_kernel()
{
    int i = blockIdx.x * blockDim.x + threadIdx.x;
    if (i >= Nn) return;
    int deg = g_indeg[i];
    int pk  = g_cnt3[i];
    int c1 = pk & 1023, c2 = (pk >> 10) & 1023, c3 = (pk >> 20) & 1023;
    g_dinv[i]        = rsqrtf((float)deg + 1.0f);
    g_dinv[Nn + i]   = rsqrtf((float)c1 + 2.0f);
    g_dinv[2*Nn + i] = rsqrtf((float)c2 + 2.0f);
    g_dinv[3*Nn + i] = rsqrtf((float)c3 + 2.0f);
}

// ---------------- GCN layer: gather-side reduction, warp per node, 4 replicas fused ----------------
__global__ void gcn_layer_kernel(const float* __restrict__ XW,      // replica-0 gather source (N x 64)
                                 const float* __restrict__ XWfull,  // full (NTOT x 64) for layer-1 self terms
                                 const float* __restrict__ bias,
                                 float* __restrict__ out,
                                 int applyRelu, int selfFull)
{
    int gw = (blockIdx.x * blockDim.x + threadIdx.x) >> 5;
    int lane = threadIdx.x & 31;
    if (gw >= Nn) return;
    int i = gw;
    float di0 = g_dinv[i];
    float di1 = g_dinv[Nn + i];
    float di2 = g_dinv[2*Nn + i];
    float di3 = g_dinv[3*Nn + i];
    float a0x=0.f,a0y=0.f,a1x=0.f,a1y=0.f,a2x=0.f,a2y=0.f,a3x=0.f,a3y=0.f;
    int beg = g_off[i], end = g_off[i+1];
    for (int k = beg; k < end; ++k) {
        int p = g_eid[k];
        int s = p & 0xFFFF;
        unsigned m = (unsigned)p >> 16;
        float ad = g_dinv[s];
        float2 r = ((const float2*)(XW + (size_t)s*Ff))[lane];
        float c0 = ad * di0;
        a0x += r.x*c0; a0y += r.y*c0;
        if (m & 1u) { float c = ad*di1; a1x += r.x*c; a1y += r.y*c; }
        if (m & 2u) { float c = ad*di2; a2x += r.x*c; a2y += r.y*c; }
        if (m & 4u) { float c = ad*di3; a3x += r.x*c; a3y += r.y*c; }
    }
    float2 s0 = ((const float2*)(XW + (size_t)i*Ff))[lane];
    float2 bv = ((const float2*)bias)[lane];
    {   // replica 0: self-loop
        float c = di0*di0;
        float ox = a0x + s0.x*c + bv.x;
        float oy = a0y + s0.y*c + bv.y;
        if (applyRelu) { ox = fmaxf(ox, 0.f); oy = fmaxf(oy, 0.f); }
        ((float2*)(out + (size_t)i*Ff))[lane] = make_float2(ox, oy);
    }
#pragma unroll
    for (int t = 1; t <= 3; ++t) {
        float dit = (t==1) ? di1 : ((t==2) ? di2 : di3);
        float ax  = (t==1) ? a1x : ((t==2) ? a2x : a3x);
        float ay  = (t==1) ? a1y : ((t==2) ? a2y : a3y);
        float car = di0 * dit;
        float2 selfrow = selfFull ? ((const float2*)(XWfull + ((size_t)t*Nn + i)*Ff))[lane] : s0;
        float cs = dit * dit;
        float ox = ax + s0.x*car + selfrow.x*cs + bv.x;
        float oy = ay + s0.y*car + selfrow.y*cs + bv.y;
        if (applyRelu) { ox = fmaxf(ox, 0.f); oy = fmaxf(oy, 0.f); }
        ((float2*)(out + ((size_t)t*Nn + i)*Ff))[lane] = make_float2(ox, oy);
    }
}

// ---------------- logits + argmax (warp per 8 rows) ----------------
__global__ void logits_kernel(const float* __restrict__ W, const float* __restrict__ b)
{
    __shared__ __align__(16) float WT[64][68];     // WT[j][k] = W[k][j]
    __shared__ float bs[64];
    __shared__ __align__(16) float hrow[8][64];
    int tid = threadIdx.x;
    for (int i = tid; i < 4096; i += 256) { int k = i >> 6, j = i & 63; WT[j][k] = W[i]; }
    if (tid < 64) bs[tid] = b[tid];
    __syncthreads();
    int wid = tid >> 5, lane = tid & 31;
    int rowbase = blockIdx.x * 64 + wid * 8;       // NTOT/64 = 3125 blocks exact
#pragma unroll
    for (int rr = 0; rr < 8; rr++) {
        int row = rowbase + rr;
        float2 v = ((const float2*)(g_x2 + (size_t)row*64))[lane];
        hrow[wid][2*lane]   = fmaxf(v.x, 0.f);
        hrow[wid][2*lane+1] = fmaxf(v.y, 0.f);
        __syncwarp();
        float l0 = bs[lane], l1 = bs[lane + 32];
#pragma unroll
        for (int k = 0; k < 64; k += 4) {
            float4 h4 = *(const float4*)&hrow[wid][k];
            float4 wa = *(const float4*)&WT[lane][k];
            float4 wb = *(const float4*)&WT[lane + 32][k];
            l0 += h4.x*wa.x + h4.y*wa.y + h4.z*wa.z + h4.w*wa.w;
            l1 += h4.x*wb.x + h4.y*wb.y + h4.z*wb.z + h4.w*wb.w;
        }
        float bv; int bi;
        if (l0 >= l1) { bv = l0; bi = lane; } else { bv = l1; bi = lane + 32; }
#pragma unroll
        for (int o = 16; o; o >>= 1) {
            float ov = __shfl_xor_sync(0xffffffffu, bv, o);
            int   oi = __shfl_xor_sync(0xffffffffu, bi, o);
            if (ov > bv || (ov == bv && oi < bi)) { bv = ov; bi = oi; }
        }
        if (lane == 0) g_cls[row] = bi;
        __syncwarp();
    }
}

// ---------------- class aggregation: hyper + softmax column sums ----------------
__global__ void classagg_kernel()
{
    __shared__ float hy[NSs][Ff];                  // 16KB
    __shared__ float cs[NSs];
    int tid = threadIdx.x;
    for (int i = tid; i < NSs*Ff; i += 256) (&hy[0][0])[i] = 0.0f;
    if (tid < NSs) cs[tid] = 0.0f;
    __syncthreads();
    int wid = tid >> 5, lane = tid & 31;
    for (int n = blockIdx.x * 8 + wid; n < Nn; n += gridDim.x * 8) {
        int c0 = g_cls[n], c1 = g_cls[Nn + n], c2 = g_cls[2*Nn + n], c3 = g_cls[3*Nn + n];
        float2 x = ((const float2*)(g_x2 + (size_t)n*64))[lane];
#define PROC(c, cnt) { \
        atomicAdd(&hy[(c)][2*lane], x.x); atomicAdd(&hy[(c)][2*lane+1], x.y); \
        if (lane == 0) atomicAdd(&cs[(c)], expf((float)(cnt)) - 1.0f); }
        { int cnt = 1 + (c1==c0) + (c2==c0) + (c3==c0); PROC(c0, cnt); }
        if (c1 != c0)                         { int cnt = 1 + (c2==c1) + (c3==c1); PROC(c1, cnt); }
        if (c2 != c0 && c2 != c1)             { int cnt = 1 + (c3==c2);            PROC(c2, cnt); }
        if (c3 != c0 && c3 != c1 && c3 != c2) {                                    PROC(c3, 1);   }
#undef PROC
    }
    __syncthreads();
    for (int i = tid; i < NSs*Ff; i += 256) atomicAdd(&g_hyper[i], (&hy[0][0])[i]);
    if (tid < NSs) atomicAdd(&g_colsum[tid], cs[tid]);
}

// ---------------- H_soft output ----------------
__global__ void hsoft_kernel(float* __restrict__ outHs)
{
    __shared__ float inv[NSs];
    int tid = threadIdx.x;
    if (tid < NSs) inv[tid] = 1.0f / g_colsum[tid];
    __syncthreads();
    int wid = tid >> 5, lane = tid & 31;
    int n = blockIdx.x * 8 + wid;                  // 6250 blocks exact
    int c0 = g_cls[n], c1 = g_cls[Nn + n], c2 = g_cls[2*Nn + n], c3 = g_cls[3*Nn + n];
    float v0 = inv[2*lane], v1 = inv[2*lane + 1];
#define APPLY(c, cnt) { int cc = (c); if ((cc >> 1) == lane) { \
        float ev = expf((float)(cnt)) * inv[cc]; if (cc & 1) v1 = ev; else v0 = ev; } }
    { int cnt = 1 + (c1==c0) + (c2==c0) + (c3==c0); APPLY(c0, cnt); }
    if (c1 != c0)                         { int cnt = 1 + (c2==c1) + (c3==c1); APPLY(c1, cnt); }
    if (c2 != c0 && c2 != c1)             { int cnt = 1 + (c3==c2);            APPLY(c2, cnt); }
    if (c3 != c0 && c3 != c1 && c3 != c2) {                                    APPLY(c3, 1);   }
#undef APPLY
    ((float2*)(outHs + (size_t)n*64))[lane] = make_float2(v0, v1);
}

// ---------------- copy hyper to output ----------------
__global__ void copy_hyper(float* __restrict__ o)
{
    int i = blockIdx.x * blockDim.x + threadIdx.x;
    if (i < NSs*Ff) o[i] = g_hyper[i];
}

// ---------------- dots = features @ hyper^T * SCALE, warp per 8 rows, 4 replica writes ----------------
__global__ void dots_kernel(const float* __restrict__ feat, float* __restrict__ outD)
{
    __shared__ __align__(16) float hyT[64][68];
    __shared__ __align__(16) float frow[8][64];
    int tid = threadIdx.x;
    for (int i = tid; i < 4096; i += 256) hyT[i >> 6][i & 63] = g_hyper[i];
    __syncthreads();
    int wid = tid >> 5, lane = tid & 31;
    int rowbase = blockIdx.x * 64 + wid * 8;
#pragma unroll
    for (int rr = 0; rr < 8; rr++) {
        int n = rowbase + rr;
        if (n >= Nn) break;
        float2 v = ((const float2*)(feat + (size_t)n*64))[lane];
        frow[wid][2*lane] = v.x; frow[wid][2*lane+1] = v.y;
        __syncwarp();
        float l0 = 0.f, l1 = 0.f;
#pragma unroll
        for (int k = 0; k < 64; k += 4) {
            float4 h4 = *(const float4*)&frow[wid][k];
            float4 wa = *(const float4*)&hyT[lane][k];
            float4 wb = *(const float4*)&hyT[lane + 32][k];
            l0 += h4.x*wa.x + h4.y*wa.y + h4.z*wa.z + h4.w*wa.w;
            l1 += h4.x*wb.x + h4.y*wb.y + h4.z*wb.z + h4.w*wb.w;
        }
        const float SCALE = 0.125f;
        l0 *= SCALE; l1 *= SCALE;
#pragma unroll
        for (int rep = 0; rep < 4; rep++) {
            float* base = outD + ((size_t)rep*Nn + n)*64;
            base[lane] = l0;
            base[lane + 32] = l1;
        }
        __syncwarp();
    }
}

// ---------------- launcher ----------------
extern "C" void kernel_launch(void* const* d_in, const int* in_sizes, int n_in,
                              void* d_out, int out_size)
{
    (void)in_sizes; (void)n_in; (void)out_size;
    const int*   ei   = (const int*)d_in[0];
    const float* feat = (const float*)d_in[1];
    const float* Wlin = (const float*)d_in[2];
    const float* blin = (const float*)d_in[3];
    const float* g0W  = (const float*)d_in[4];
    const float* g0b  = (const float*)d_in[5];
    const float* g1W  = (const float*)d_in[6];
    const float* g1b  = (const float*)d_in[7];
    const float* l1W  = (const float*)d_in[8];
    const float* l1b  = (const float*)d_in[9];

    float* out   = (float*)d_out;
    float* outHs = out;                                    // (N, NS)
    float* outHy = out + (size_t)Nn*NSs;                   // (NS, F)
    float* outD  = out + (size_t)Nn*NSs + (size_t)NSs*Ff;  // (NTOT, NS)

    float *p_xw0, *p_h1, *p_xw1, *p_x2;
    cudaGetSymbolAddress((void**)&p_xw0, g_xw0);
    cudaGetSymbolAddress((void**)&p_h1,  g_h1);
    cudaGetSymbolAddress((void**)&p_xw1, g_xw1);
    cudaGetSymbolAddress((void**)&p_x2,  g_x2);

    init_kernel<<<(Nn + 255)/256, 256>>>();

    const int GB_N    = (Nn + 127) / 128;     // 391
    const int GB_NTOT = (NTOT + 127) / 128;   // 1563

    // per-replica linear transforms -> normalized difference rows (fused)
    gemm_rb<<<dim3(GB_N, 3), 128>>>(feat, Wlin, blin, nullptr, Nn, 0, 1);

    edge_kernel<<<(Ee*16)/256, 256>>>(ei, feat);
    scan_kernel<<<1, 1024>>>();
    fill_kernel<<<(Ee + 255)/256, 256>>>(ei);
    dinv_kernel<<<(Nn + 255)/256, 256>>>();

    // layer 0 (xw identical across replicas)
    gemm_rb<<<dim3(GB_N, 1), 128>>>(feat, g0W, nullptr, p_xw0, Nn, 1, 0);
    gcn_layer_kernel<<<(Nn + 7)/8, 256>>>(p_xw0, p_xw0, g0b, p_h1, 1, 0);

    // layer 1
    gemm_rb<<<dim3(GB_NTOT, 1), 128>>>(p_h1, g1W, nullptr, p_xw1, NTOT, 0, 0);
    gcn_layer_kernel<<<(Nn + 7)/8, 256>>>(p_xw1, p_xw1, g1b, p_x2, 0, 1);

    // logits + argmax
    logits_kernel<<<NTOT/64, 256>>>(l1W, l1b);

    // hyperedge features + softmax column sums
    classagg_kernel<<<128, 256>>>();

    // outputs
    hsoft_kernel<<<Nn/8, 256>>>(outHs);
    copy_hyper<<<16, 256>>>(outHy);
    dots_kernel<<<(Nn + 63)/64, 256>>>(feat, outD);
}

// round 5
// speedup vs baseline: 2.0514x; 1.0378x over previous
#include <cuda_runtime.h>
#include <math.h>

#define Nn 50000
#define Ee 800000
#define Ff 64
#define Tt 3
#define NSs 64
#define NTOT (4*Nn)
#define SCAN_TILE 4096
#define SCAN_BLOCKS ((Nn + SCAN_TILE - 1) / SCAN_TILE)   // 13

// ---------------- scratch (device globals; no allocation allowed) ----------------
__device__ __align__(16) float g_diff[Nn*192];   // per node: 3 normalized-difference rows
__device__ unsigned char g_mask[Ee];
__device__ int g_indeg[Nn];
__device__ int g_cnt3[Nn];                        // packed replica counts (10 bits each)
__device__ int g_off[Nn+1];
__device__ int g_fill[Nn];
__device__ int g_eid[Ee];                         // packed: src | (mask<<16)
__device__ int g_bsum[SCAN_BLOCKS];
__device__ int g_bcarry[SCAN_BLOCKS];
__device__ float g_dinv[4*Nn];
__device__ __align__(16) float g_xw0[Nn*Ff];
__device__ __align__(16) float g_h1[NTOT*Ff];
__device__ __align__(16) float g_xw1[NTOT*Ff];
__device__ __align__(16) float g_x2[NTOT*Ff];
__device__ int g_cls[NTOT];
__device__ __align__(16) float g_hyper[NSs*Ff];
__device__ float g_colsum[NSs];

// ---------------- init ----------------
__global__ void init_kernel()
{
    int i = blockIdx.x * blockDim.x + threadIdx.x;
    if (i < Nn) { g_indeg[i] = 0; g_fill[i] = 0; g_cnt3[i] = 0; }
    if (i < NSs*Ff) g_hyper[i] = 0.0f;
    if (i < NSs) g_colsum[i] = (float)Nn;
}

// ---------------- register-blocked GEMM: out = (relu?)X @ W (+bias), K=N=64 ----------------
__global__ __launch_bounds__(128)
void gemm_rb(const float* __restrict__ X, const float* __restrict__ W,
             const float* __restrict__ bias, float* __restrict__ out,
             int rows, int relu_in, int diffMode)
{
    __shared__ float As[128*64];   // 32KB
    __shared__ float Bs[64*64];    // 16KB
    const int tid = threadIdx.x;
    const int tx = tid & 7;
    const int ty = tid >> 3;
    const int b  = blockIdx.y;
    const int row0 = blockIdx.x * 128;

    const float* Wb = W + (size_t)b * 4096;

#pragma unroll
    for (int it = 0; it < 16; it++) {
        int idx = tid + it * 128;
        int r = idx >> 4, c4 = (idx & 15) << 2;
        int gr = row0 + r;
        float4 v = make_float4(0.f, 0.f, 0.f, 0.f);
        if (gr < rows) v = *(const float4*)&X[(size_t)gr*64 + c4];
        if (relu_in) { v.x = fmaxf(v.x,0.f); v.y = fmaxf(v.y,0.f); v.z = fmaxf(v.z,0.f); v.w = fmaxf(v.w,0.f); }
        *(float4*)&As[r*64 + c4] = v;
    }
#pragma unroll
    for (int it = 0; it < 8; it++) {
        int idx = tid + it * 128;
        int k = idx >> 4, c4 = (idx & 15) << 2;
        *(float4*)&Bs[k*64 + c4] = *(const float4*)&Wb[k*64 + c4];
    }
    __syncthreads();

    float acc[8][8];
#pragma unroll
    for (int i = 0; i < 8; i++)
#pragma unroll
        for (int j = 0; j < 8; j++) acc[i][j] = 0.f;

    const int rbase = ty * 8;
    const int c0 = tx * 8;
#pragma unroll
    for (int k0 = 0; k0 < 64; k0 += 4) {
        float4 a[8];
#pragma unroll
        for (int i = 0; i < 8; i++) a[i] = *(const float4*)&As[(rbase+i)*64 + k0];
#pragma unroll
        for (int kk = 0; kk < 4; kk++) {
            float4 b0 = *(const float4*)&Bs[(k0+kk)*64 + c0];
            float4 b1 = *(const float4*)&Bs[(k0+kk)*64 + c0 + 4];
            float bb[8] = {b0.x,b0.y,b0.z,b0.w,b1.x,b1.y,b1.z,b1.w};
#pragma unroll
            for (int i = 0; i < 8; i++) {
                float av = (kk==0) ? a[i].x : (kk==1) ? a[i].y : (kk==2) ? a[i].z : a[i].w;
#pragma unroll
                for (int j = 0; j < 8; j++) acc[i][j] += av * bb[j];
            }
        }
    }

    float bj[8];
#pragma unroll
    for (int j = 0; j < 8; j++) bj[j] = bias ? bias[(size_t)b*64 + c0 + j] : 0.f;

    if (!diffMode) {
        float* outb = out + (size_t)b * rows * 64;
#pragma unroll
        for (int i = 0; i < 8; i++) {
            int gr = row0 + rbase + i;
            if (gr >= rows) continue;
            float v[8];
#pragma unroll
            for (int j = 0; j < 8; j++) v[j] = acc[i][j] + bj[j];
            *(float4*)&outb[(size_t)gr*64 + c0]     = make_float4(v[0],v[1],v[2],v[3]);
            *(float4*)&outb[(size_t)gr*64 + c0 + 4] = make_float4(v[4],v[5],v[6],v[7]);
        }
    } else {
#pragma unroll
        for (int i = 0; i < 8; i++) {
            int gr = row0 + rbase + i;
            float v[8], x[8];
            float sqv = 0.f, sqx = 0.f;
#pragma unroll
            for (int j = 0; j < 8; j++) {
                v[j] = acc[i][j] + bj[j];
                x[j] = As[(rbase+i)*64 + c0 + j];
                sqv += v[j]*v[j];
                sqx += x[j]*x[j];
            }
            sqv += __shfl_xor_sync(0xffffffffu, sqv, 1);
            sqv += __shfl_xor_sync(0xffffffffu, sqv, 2);
            sqv += __shfl_xor_sync(0xffffffffu, sqv, 4);
            sqx += __shfl_xor_sync(0xffffffffu, sqx, 1);
            sqx += __shfl_xor_sync(0xffffffffu, sqx, 2);
            sqx += __shfl_xor_sync(0xffffffffu, sqx, 4);
            float itn = 1.0f / fmaxf(sqrtf(sqv), 1e-8f);
            float ixn = 1.0f / fmaxf(sqrtf(sqx), 1e-8f);
            if (gr < rows) {
                float d[8];
#pragma unroll
                for (int j = 0; j < 8; j++) d[j] = v[j]*itn - x[j]*ixn;
                float* dst = &g_diff[(size_t)gr*192 + b*64 + c0];
                *(float4*)&dst[0] = make_float4(d[0],d[1],d[2],d[3]);
                *(float4*)&dst[4] = make_float4(d[4],d[5],d[6],d[7]);
            }
        }
    }
}

// ---------------- per-edge masks; 16 lanes per edge, 2 edges per group ----------------
__global__ void edge_kernel(const int* __restrict__ ei, const float* __restrict__ feat)
{
    int gid = blockIdx.x * blockDim.x + threadIdx.x;
    int grp = gid >> 4;                 // each group does edges 2*grp, 2*grp+1
    int q = threadIdx.x & 15;
    int e0 = grp * 2;
    if (e0 >= Ee) return;
    int s0 = ei[e0], d0 = ei[Ee + e0];
    int s1 = ei[e0+1], d1 = ei[Ee + e0 + 1];

    const float4* dp0 = (const float4*)(g_diff + (size_t)s0*192);
    const float4* dp1 = (const float4*)(g_diff + (size_t)s1*192);
    float4 fdA = ((const float4*)(feat + (size_t)d0*64))[q];
    float4 fdB = ((const float4*)(feat + (size_t)d1*64))[q];
    float4 a0 = dp0[q], a1 = dp0[16 + q], a2 = dp0[32 + q];
    float4 b0 = dp1[q], b1 = dp1[16 + q], b2 = dp1[32 + q];

    float pA0 = a0.x*fdA.x + a0.y*fdA.y + a0.z*fdA.z + a0.w*fdA.w;
    float pA1 = a1.x*fdA.x + a1.y*fdA.y + a1.z*fdA.z + a1.w*fdA.w;
    float pA2 = a2.x*fdA.x + a2.y*fdA.y + a2.z*fdA.z + a2.w*fdA.w;
    float pB0 = b0.x*fdB.x + b0.y*fdB.y + b0.z*fdB.z + b0.w*fdB.w;
    float pB1 = b1.x*fdB.x + b1.y*fdB.y + b1.z*fdB.z + b1.w*fdB.w;
    float pB2 = b2.x*fdB.x + b2.y*fdB.y + b2.z*fdB.z + b2.w*fdB.w;
#pragma unroll
    for (int o = 8; o; o >>= 1) {
        pA0 += __shfl_xor_sync(0xffffffffu, pA0, o);
        pA1 += __shfl_xor_sync(0xffffffffu, pA1, o);
        pA2 += __shfl_xor_sync(0xffffffffu, pA2, o);
        pB0 += __shfl_xor_sync(0xffffffffu, pB0, o);
        pB1 += __shfl_xor_sync(0xffffffffu, pB1, o);
        pB2 += __shfl_xor_sync(0xffffffffu, pB2, o);
    }
    if (q == 0) {
        unsigned m = 0; int pk = 0;
        if (pA0 > 0.f) { m |= 1u; pk += 1; }
        if (pA1 > 0.f) { m |= 2u; pk += 1 << 10; }
        if (pA2 > 0.f) { m |= 4u; pk += 1 << 20; }
        g_mask[e0] = (unsigned char)m;
        atomicAdd(&g_indeg[d0], 1);
        if (pk) atomicAdd(&g_cnt3[d0], pk);

        m = 0; pk = 0;
        if (pB0 > 0.f) { m |= 1u; pk += 1; }
        if (pB1 > 0.f) { m |= 2u; pk += 1 << 10; }
        if (pB2 > 0.f) { m |= 4u; pk += 1 << 20; }
        g_mask[e0+1] = (unsigned char)m;
        atomicAdd(&g_indeg[d1], 1);
        if (pk) atomicAdd(&g_cnt3[d1], pk);
    }
}

// ---------------- scan pass A: per-block exclusive scan + block sums ----------------
__global__ void scanA_kernel()
{
    __shared__ int wsum[32];
    int tid = threadIdx.x, lane = tid & 31, wid = tid >> 5;
    int idx4 = blockIdx.x * SCAN_TILE + tid * 4;
    int4 v = make_int4(0,0,0,0);
    if (idx4 + 3 < Nn) v = *(const int4*)&g_indeg[idx4];
    else if (idx4 < Nn) {
        v.x = g_indeg[idx4];
        if (idx4+1 < Nn) v.y = g_indeg[idx4+1];
        if (idx4+2 < Nn) v.z = g_indeg[idx4+2];
    }
    int local = v.x + v.y + v.z + v.w;
    int incl = local;
#pragma unroll
    for (int o = 1; o < 32; o <<= 1) {
        int t = __shfl_up_sync(0xffffffffu, incl, o);
        if (lane >= o) incl += t;
    }
    if (lane == 31) wsum[wid] = incl;
    __syncthreads();
    if (wid == 0) {
        int s = wsum[lane];
        int si = s;
#pragma unroll
        for (int o = 1; o < 32; o <<= 1) {
            int t = __shfl_up_sync(0xffffffffu, si, o);
            if (lane >= o) si += t;
        }
        wsum[lane] = si - s;
        if (lane == 31) g_bsum[blockIdx.x] = si;
    }
    __syncthreads();
    int excl = wsum[wid] + (incl - local);
    if (idx4 + 3 < Nn) {
        *(int4*)&g_off[idx4] = make_int4(excl, excl+v.x, excl+v.x+v.y, excl+v.x+v.y+v.z);
    } else if (idx4 < Nn) {
        g_off[idx4] = excl;
        if (idx4+1 < Nn) g_off[idx4+1] = excl + v.x;
        if (idx4+2 < Nn) g_off[idx4+2] = excl + v.x + v.y;
    }
}

// ---------------- scan pass B: scan block sums (1 warp) ----------------
__global__ void scanB_kernel()
{
    int lane = threadIdx.x;
    int s = (lane < SCAN_BLOCKS) ? g_bsum[lane] : 0;
    int si = s;
#pragma unroll
    for (int o = 1; o < 32; o <<= 1) {
        int t = __shfl_up_sync(0xffffffffu, si, o);
        if (lane >= o) si += t;
    }
    if (lane < SCAN_BLOCKS) g_bcarry[lane] = si - s;
    if (lane == 31) g_off[Nn] = si;     // total (lanes >= SCAN_BLOCKS added 0)
}

// ---------------- scan pass C: add carries + compute dinv (fused) ----------------
__global__ void scanC_kernel()
{
    int tid = threadIdx.x;
    int carry = g_bcarry[blockIdx.x];
    int idx4 = blockIdx.x * SCAN_TILE + tid * 4;
    if (idx4 >= Nn) return;
    if (idx4 + 3 < Nn) {
        int4 o = *(const int4*)&g_off[idx4];
        o.x += carry; o.y += carry; o.z += carry; o.w += carry;
        *(int4*)&g_off[idx4] = o;
        int4 dg = *(const int4*)&g_indeg[idx4];
        int4 pk = *(const int4*)&g_cnt3[idx4];
        int dgs[4] = {dg.x, dg.y, dg.z, dg.w};
        int pks[4] = {pk.x, pk.y, pk.z, pk.w};
#pragma unroll
        for (int j = 0; j < 4; j++) {
            int i = idx4 + j;
            g_dinv[i]        = rsqrtf((float)dgs[j] + 1.0f);
            g_dinv[Nn + i]   = rsqrtf((float)(pks[j] & 1023) + 2.0f);
            g_dinv[2*Nn + i] = rsqrtf((float)((pks[j] >> 10) & 1023) + 2.0f);
            g_dinv[3*Nn + i] = rsqrtf((float)((pks[j] >> 20) & 1023) + 2.0f);
        }
    } else {
        for (int i = idx4; i < Nn; i++) {
            g_off[i] += carry;
            int pk = g_cnt3[i];
            g_dinv[i]        = rsqrtf((float)g_indeg[i] + 1.0f);
            g_dinv[Nn + i]   = rsqrtf((float)(pk & 1023) + 2.0f);
            g_dinv[2*Nn + i] = rsqrtf((float)((pk >> 10) & 1023) + 2.0f);
            g_dinv[3*Nn + i] = rsqrtf((float)((pk >> 20) & 1023) + 2.0f);
        }
    }
}

// ---------------- CSR fill (packed src|mask) ----------------
__global__ void fill_kernel(const int* __restrict__ ei)
{
    int e = blockIdx.x * blockDim.x + threadIdx.x;
    if (e >= Ee) return;
    int s = ei[e];
    int d = ei[Ee + e];
    unsigned m = g_mask[e];
    int p = g_off[d] + atomicAdd(&g_fill[d], 1);
    g_eid[p] = s | ((int)m << 16);
}

// ---------------- GCN layer: gather-side reduction, warp per node, 4 replicas fused ----------------
__global__ void gcn_layer_kernel(const float* __restrict__ XW,
                                 const float* __restrict__ XWfull,
                                 const float* __restrict__ bias,
                                 float* __restrict__ out,
                                 int applyRelu, int selfFull)
{
    int gw = (blockIdx.x * blockDim.x + threadIdx.x) >> 5;
    int lane = threadIdx.x & 31;
    if (gw >= Nn) return;
    int i = gw;
    float di0 = g_dinv[i];
    float di1 = g_dinv[Nn + i];
    float di2 = g_dinv[2*Nn + i];
    float di3 = g_dinv[3*Nn + i];
    float a0x=0.f,a0y=0.f,a1x=0.f,a1y=0.f,a2x=0.f,a2y=0.f,a3x=0.f,a3y=0.f;
    int beg = g_off[i], end = g_off[i+1];
    int k = beg;
    for (; k + 4 <= end; k += 4) {
        int p0 = g_eid[k], p1 = g_eid[k+1], p2 = g_eid[k+2], p3 = g_eid[k+3];
        int s0 = p0 & 0xFFFF, s1 = p1 & 0xFFFF, s2 = p2 & 0xFFFF, s3 = p3 & 0xFFFF;
        float ad0 = g_dinv[s0], ad1 = g_dinv[s1], ad2 = g_dinv[s2], ad3 = g_dinv[s3];
        float2 r0 = ((const float2*)(XW + (size_t)s0*Ff))[lane];
        float2 r1 = ((const float2*)(XW + (size_t)s1*Ff))[lane];
        float2 r2 = ((const float2*)(XW + (size_t)s2*Ff))[lane];
        float2 r3 = ((const float2*)(XW + (size_t)s3*Ff))[lane];
        unsigned m0 = (unsigned)p0 >> 16, m1 = (unsigned)p1 >> 16;
        unsigned m2 = (unsigned)p2 >> 16, m3 = (unsigned)p3 >> 16;
#define ACC(r, ad, m) { \
        float c0 = (ad) * di0; \
        a0x += r.x*c0; a0y += r.y*c0; \
        if ((m) & 1u) { float c = (ad)*di1; a1x += r.x*c; a1y += r.y*c; } \
        if ((m) & 2u) { float c = (ad)*di2; a2x += r.x*c; a2y += r.y*c; } \
        if ((m) & 4u) { float c = (ad)*di3; a3x += r.x*c; a3y += r.y*c; } }
        ACC(r0, ad0, m0); ACC(r1, ad1, m1); ACC(r2, ad2, m2); ACC(r3, ad3, m3);
    }
    for (; k < end; ++k) {
        int p = g_eid[k];
        int s = p & 0xFFFF;
        unsigned m = (unsigned)p >> 16;
        float ad = g_dinv[s];
        float2 r = ((const float2*)(XW + (size_t)s*Ff))[lane];
        ACC(r, ad, m);
    }
#undef ACC
    float2 s0 = ((const float2*)(XW + (size_t)i*Ff))[lane];
    float2 bv = ((const float2*)bias)[lane];
    {
        float c = di0*di0;
        float ox = a0x + s0.x*c + bv.x;
        float oy = a0y + s0.y*c + bv.y;
        if (applyRelu) { ox = fmaxf(ox, 0.f); oy = fmaxf(oy, 0.f); }
        ((float2*)(out + (size_t)i*Ff))[lane] = make_float2(ox, oy);
    }
#pragma unroll
    for (int t = 1; t <= 3; ++t) {
        float dit = (t==1) ? di1 : ((t==2) ? di2 : di3);
        float ax  = (t==1) ? a1x : ((t==2) ? a2x : a3x);
        float ay  = (t==1) ? a1y : ((t==2) ? a2y : a3y);
        float car = di0 * dit;
        float2 selfrow = selfFull ? ((const float2*)(XWfull + ((size_t)t*Nn + i)*Ff))[lane] : s0;
        float cs = dit * dit;
        float ox = ax + s0.x*car + selfrow.x*cs + bv.x;
        float oy = ay + s0.y*car + selfrow.y*cs + bv.y;
        if (applyRelu) { ox = fmaxf(ox, 0.f); oy = fmaxf(oy, 0.f); }
        ((float2*)(out + ((size_t)t*Nn + i)*Ff))[lane] = make_float2(ox, oy);
    }
}

// ---------------- logits + argmax (warp per 8 rows) ----------------
__global__ void logits_kernel(const float* __restrict__ W, const float* __restrict__ b)
{
    __shared__ __align__(16) float WT[64][68];
    __shared__ float bs[64];
    __shared__ __align__(16) float hrow[8][64];
    int tid = threadIdx.x;
    for (int i = tid; i < 4096; i += 256) { int k = i >> 6, j = i & 63; WT[j][k] = W[i]; }
    if (tid < 64) bs[tid] = b[tid];
    __syncthreads();
    int wid = tid >> 5, lane = tid & 31;
    int rowbase = blockIdx.x * 64 + wid * 8;
#pragma unroll
    for (int rr = 0; rr < 8; rr++) {
        int row = rowbase + rr;
        float2 v = ((const float2*)(g_x2 + (size_t)row*64))[lane];
        hrow[wid][2*lane]   = fmaxf(v.x, 0.f);
        hrow[wid][2*lane+1] = fmaxf(v.y, 0.f);
        __syncwarp();
        float l0 = bs[lane], l1 = bs[lane + 32];
#pragma unroll
        for (int k = 0; k < 64; k += 4) {
            float4 h4 = *(const float4*)&hrow[wid][k];
            float4 wa = *(const float4*)&WT[lane][k];
            float4 wb = *(const float4*)&WT[lane + 32][k];
            l0 += h4.x*wa.x + h4.y*wa.y + h4.z*wa.z + h4.w*wa.w;
            l1 += h4.x*wb.x + h4.y*wb.y + h4.z*wb.z + h4.w*wb.w;
        }
        float bv; int bi;
        if (l0 >= l1) { bv = l0; bi = lane; } else { bv = l1; bi = lane + 32; }
#pragma unroll
        for (int o = 16; o; o >>= 1) {
            float ov = __shfl_xor_sync(0xffffffffu, bv, o);
            int   oi = __shfl_xor_sync(0xffffffffu, bi, o);
            if (ov > bv || (ov == bv && oi < bi)) { bv = ov; bi = oi; }
        }
        if (lane == 0) g_cls[row] = bi;
        __syncwarp();
    }
}

// ---------------- class aggregation: hyper + softmax column sums ----------------
__global__ void classagg_kernel()
{
    __shared__ float hy[NSs][Ff];
    __shared__ float cs[NSs];
    int tid = threadIdx.x;
    for (int i = tid; i < NSs*Ff; i += 256) (&hy[0][0])[i] = 0.0f;
    if (tid < NSs) cs[tid] = 0.0f;
    __syncthreads();
    int wid = tid >> 5, lane = tid & 31;
    for (int n = blockIdx.x * 8 + wid; n < Nn; n += gridDim.x * 8) {
        int c0 = g_cls[n], c1 = g_cls[Nn + n], c2 = g_cls[2*Nn + n], c3 = g_cls[3*Nn + n];
        float2 x = ((const float2*)(g_x2 + (size_t)n*64))[lane];
#define PROC(c, cnt) { \
        atomicAdd(&hy[(c)][2*lane], x.x); atomicAdd(&hy[(c)][2*lane+1], x.y); \
        if (lane == 0) atomicAdd(&cs[(c)], expf((float)(cnt)) - 1.0f); }
        { int cnt = 1 + (c1==c0) + (c2==c0) + (c3==c0); PROC(c0, cnt); }
        if (c1 != c0)                         { int cnt = 1 + (c2==c1) + (c3==c1); PROC(c1, cnt); }
        if (c2 != c0 && c2 != c1)             { int cnt = 1 + (c3==c2);            PROC(c2, cnt); }
        if (c3 != c0 && c3 != c1 && c3 != c2) {                                    PROC(c3, 1);   }
#undef PROC
    }
    __syncthreads();
    for (int i = tid; i < NSs*Ff; i += 256) atomicAdd(&g_hyper[i], (&hy[0][0])[i]);
    if (tid < NSs) atomicAdd(&g_colsum[tid], cs[tid]);
}

// ---------------- H_soft output ----------------
__global__ void hsoft_kernel(float* __restrict__ outHs)
{
    __shared__ float inv[NSs];
    int tid = threadIdx.x;
    if (tid < NSs) inv[tid] = 1.0f / g_colsum[tid];
    __syncthreads();
    int wid = tid >> 5, lane = tid & 31;
    int n = blockIdx.x * 8 + wid;
    int c0 = g_cls[n], c1 = g_cls[Nn + n], c2 = g_cls[2*Nn + n], c3 = g_cls[3*Nn + n];
    float v0 = inv[2*lane], v1 = inv[2*lane + 1];
#define APPLY(c, cnt) { int cc = (c); if ((cc >> 1) == lane) { \
        float ev = expf((float)(cnt)) * inv[cc]; if (cc & 1) v1 = ev; else v0 = ev; } }
    { int cnt = 1 + (c1==c0) + (c2==c0) + (c3==c0); APPLY(c0, cnt); }
    if (c1 != c0)                         { int cnt = 1 + (c2==c1) + (c3==c1); APPLY(c1, cnt); }
    if (c2 != c0 && c2 != c1)             { int cnt = 1 + (c3==c2);            APPLY(c2, cnt); }
    if (c3 != c0 && c3 != c1 && c3 != c2) {                                    APPLY(c3, 1);   }
#undef APPLY
    ((float2*)(outHs + (size_t)n*64))[lane] = make_float2(v0, v1);
}

// ---------------- copy hyper to output ----------------
__global__ void copy_hyper(float* __restrict__ o)
{
    int i = blockIdx.x * blockDim.x + threadIdx.x;
    if (i < NSs*Ff) o[i] = g_hyper[i];
}

// ---------------- dots = features @ hyper^T * SCALE ----------------
__global__ void dots_kernel(const float* __restrict__ feat, float* __restrict__ outD)
{
    __shared__ __align__(16) float hyT[64][68];
    __shared__ __align__(16) float frow[8][64];
    int tid = threadIdx.x;
    for (int i = tid; i < 4096; i += 256) hyT[i >> 6][i & 63] = g_hyper[i];
    __syncthreads();
    int wid = tid >> 5, lane = tid & 31;
    int rowbase = blockIdx.x * 64 + wid * 8;
#pragma unroll
    for (int rr = 0; rr < 8; rr++) {
        int n = rowbase + rr;
        if (n >= Nn) break;
        float2 v = ((const float2*)(feat + (size_t)n*64))[lane];
        frow[wid][2*lane] = v.x; frow[wid][2*lane+1] = v.y;
        __syncwarp();
        float l0 = 0.f, l1 = 0.f;
#pragma unroll
        for (int k = 0; k < 64; k += 4) {
            float4 h4 = *(const float4*)&frow[wid][k];
            float4 wa = *(const float4*)&hyT[lane][k];
            float4 wb = *(const float4*)&hyT[lane + 32][k];
            l0 += h4.x*wa.x + h4.y*wa.y + h4.z*wa.z + h4.w*wa.w;
            l1 += h4.x*wb.x + h4.y*wb.y + h4.z*wb.z + h4.w*wb.w;
        }
        const float SCALE = 0.125f;
        l0 *= SCALE; l1 *= SCALE;
#pragma unroll
        for (int rep = 0; rep < 4; rep++) {
            float* base = outD + ((size_t)rep*Nn + n)*64;
            base[lane] = l0;
            base[lane + 32] = l1;
        }
        __syncwarp();
    }
}

// ---------------- launcher ----------------
extern "C" void kernel_launch(void* const* d_in, const int* in_sizes, int n_in,
                              void* d_out, int out_size)
{
    (void)in_sizes; (void)n_in; (void)out_size;
    const int*   ei   = (const int*)d_in[0];
    const float* feat = (const float*)d_in[1];
    const float* Wlin = (const float*)d_in[2];
    const float* blin = (const float*)d_in[3];
    const float* g0W  = (const float*)d_in[4];
    const float* g0b  = (const float*)d_in[5];
    const float* g1W  = (const float*)d_in[6];
    const float* g1b  = (const float*)d_in[7];
    const float* l1W  = (const float*)d_in[8];
    const float* l1b  = (const float*)d_in[9];

    float* out   = (float*)d_out;
    float* outHs = out;
    float* outHy = out + (size_t)Nn*NSs;
    float* outD  = out + (size_t)Nn*NSs + (size_t)NSs*Ff;

    float *p_xw0, *p_h1, *p_xw1, *p_x2;
    cudaGetSymbolAddress((void**)&p_xw0, g_xw0);
    cudaGetSymbolAddress((void**)&p_h1,  g_h1);
    cudaGetSymbolAddress((void**)&p_xw1, g_xw1);
    cudaGetSymbolAddress((void**)&p_x2,  g_x2);

    init_kernel<<<(Nn + 255)/256, 256>>>();

    const int GB_N    = (Nn + 127) / 128;
    const int GB_NTOT = (NTOT + 127) / 128;

    gemm_rb<<<dim3(GB_N, 3), 128>>>(feat, Wlin, blin, nullptr, Nn, 0, 1);

    edge_kernel<<<(Ee/2*16 + 255)/256, 256>>>(ei, feat);
    scanA_kernel<<<SCAN_BLOCKS, 1024>>>();
    scanB_kernel<<<1, 32>>>();
    scanC_kernel<<<SCAN_BLOCKS, 1024>>>();
    fill_kernel<<<(Ee + 255)/256, 256>>>(ei);

    gemm_rb<<<dim3(GB_N, 1), 128>>>(feat, g0W, nullptr, p_xw0, Nn, 1, 0);
    gcn_layer_kernel<<<(Nn + 7)/8, 256>>>(p_xw0, p_xw0, g0b, p_h1, 1, 0);

    gemm_rb<<<dim3(GB_NTOT, 1), 128>>>(p_h1, g1W, nullptr, p_xw1, NTOT, 0, 0);
    gcn_layer_kernel<<<(Nn + 7)/8, 256>>>(p_xw1, p_xw1, g1b, p_x2, 0, 1);

    logits_kernel<<<NTOT/64, 256>>>(l1W, l1b);
    classagg_kernel<<<128, 256>>>();

    hsoft_kernel<<<Nn/8, 256>>>(outHs);
    copy_hyper<<<16, 256>>>(outHy);
    dots_kernel<<<(Nn + 63)/64, 256>>>(feat, outD);
}